// round 15
// baseline (speedup 1.0000x reference)
#include <cuda_runtime.h>
#include <math.h>

// Shapes (fixed for this problem)
#define B_ 4
#define P_ 32768
#define C_ 8
#define F_ 32
#define D_ 64
#define H_ 64

#define TP 64         // points per CTA tile
#define XLD 68        // padded row stride (floats); 68*4=272B = 17*16B -> float4/u64 aligned rows

// ---- precomputed per-(b,c) data (tiny scratch; __device__ globals, no allocs) ----
__device__ float g_M[B_ * C_ * 3 * H_];   // M[b,c][i][h] = (W_feat @ z[b,c] @ W0_mid)[i,h]
__device__ float g_zi[B_ * C_ * H_];      // zi_proj[b,c][h] = z_inv @ W0[65:129] + b0
__device__ float g_G[16];                 // G = W_feat @ W_feat^T (3x3, padded)

// ---- shared memory layout (in floats) ----
// XS holds relu(x) (raw x lives in registers); HS holds relu(h).
// WPA/WPB hold pair-interleaved weights: u64[kp*H + c] = (W[2kp][c], W[2kp+1][c])
#define OFF_XS   0
#define OFF_HS   (TP * XLD)                 // 4352
#define OFF_WPA  (2 * TP * XLD)             // 8704   (4096 floats = 2048 u64)
#define OFF_WPB  (OFF_WPA + H_ * H_)        // 12800
#define OFF_QS   (OFF_WPB + H_ * H_)        // 16896  (q0,q1,q2,s per point)
#define OFF_M    (OFF_QS + TP * 4)          // 17152
#define OFF_ZI   (OFF_M + C_ * 3 * H_)      // 18688
#define OFF_W0   (OFF_ZI + C_ * H_)         // 19200  (W0 row 0)
#define OFF_WOUT (OFF_W0 + H_)              // 19264
#define SMEM_FLOATS (OFF_WOUT + H_)         // 19328
#define SMEM_BYTES  (SMEM_FLOATS * 4)       // 77312 B -> 2 CTAs/SM

// =====================================================================
// Precompute kernel: 32 blocks (one per (b,c)), 64 threads (h index)
// =====================================================================
__global__ void vson_precompute_kernel(const float* __restrict__ z,
                                       const float* __restrict__ W_feat,
                                       const float* __restrict__ W_dir,
                                       const float* __restrict__ W0,
                                       const float* __restrict__ b0) {
    __shared__ float s_zinv[D_];
    __shared__ float s_Z0[F_ * H_];

    const int bc = blockIdx.x;          // b*C + c
    const int e = threadIdx.x;          // 0..63
    const float* zb = z + bc * F_ * D_; // z[b,c] : (F, D) row-major

    // z_inv[e] = sum_f z[f,e] * (sum_d z[f,d] * W_dir[d,e])
    float zi = 0.f;
    for (int f = 0; f < F_; f++) {
        float zd = 0.f;
        for (int d = 0; d < D_; d++) zd += zb[f * D_ + d] * W_dir[d * D_ + e];
        zi += zb[f * D_ + e] * zd;
    }
    s_zinv[e] = zi;
    __syncthreads();

    // zi_proj[h] = sum_d z_inv[d] * W0[1+D+d, h] + b0[h]
    {
        float zp = b0[e];
        for (int d = 0; d < D_; d++) zp += s_zinv[d] * W0[(1 + D_ + d) * H_ + e];
        g_zi[bc * H_ + e] = zp;
    }

    // Z0[f,h] = sum_d z[f,d] * W0[1+d, h]
    for (int f = 0; f < F_; f++) {
        float s = 0.f;
        for (int d = 0; d < D_; d++) s += zb[f * D_ + d] * W0[(1 + d) * H_ + e];
        s_Z0[f * H_ + e] = s;
    }
    __syncthreads();

    // M[i,h] = sum_f W_feat[i,f] * Z0[f,h]
    for (int i = 0; i < 3; i++) {
        float s = 0.f;
        for (int f = 0; f < F_; f++) s += W_feat[i * F_ + f] * s_Z0[f * H_ + e];
        g_M[(bc * 3 + i) * H_ + e] = s;
    }

    // G (3x3) once
    if (bc == 0 && e < 9) {
        int i = e / 3, j = e % 3;
        float s = 0.f;
        for (int f = 0; f < F_; f++) s += W_feat[i * F_ + f] * W_feat[j * F_ + f];
        g_G[e] = s;
    }
}

// =====================================================================
// f32x2 packed helpers (Blackwell native FFMA2 path)
// =====================================================================
__device__ __forceinline__ unsigned long long pack2(float lo, float hi) {
    unsigned long long r;
    asm("mov.b64 %0, {%1, %2};" : "=l"(r) : "f"(lo), "f"(hi));
    return r;
}
// acc = a*b + acc, lanewise on packed f32x2 (one FFMA2 instruction)
__device__ __forceinline__ void ffma2(unsigned long long& acc,
                                      unsigned long long a,
                                      unsigned long long b) {
    asm("fma.rn.f32x2 %0, %1, %2, %0;" : "+l"(acc) : "l"(a), "l"(b));
}
// horizontal sum of the two f32 lanes
__device__ __forceinline__ float red2(unsigned long long v) {
    float lo, hi;
    asm("mov.b64 {%0, %1}, %2;" : "=f"(lo), "=f"(hi) : "l"(v));
    return lo + hi;
}

// =====================================================================
// Pair-GEMV: acc[i*4+c] lanes accumulate (even-k, odd-k) partial products of
//   sum_k act[rb[i]+k] * W[k][col+c]
// over k=0..63. Activations in smem are ALREADY activated (relu applied by
// producer). Weights come from the pair-interleaved u64 table Wp.
// Zero packs, zero relu in the loop: pure LDS + FFMA2.
// =====================================================================
__device__ __forceinline__ void gemv64_pair(const float* __restrict__ sm_,
                                            int in_off, int wp_off,
                                            const int rb[4], int col,
                                            unsigned long long acc[16]) {
    const unsigned long long* Wp = (const unsigned long long*)(sm_ + wp_off);
#pragma unroll 4
    for (int k0 = 0; k0 < H_; k0 += 4) {
        ulonglong2 a[4];
#pragma unroll
        for (int i = 0; i < 4; i++)
            a[i] = *(const ulonglong2*)(sm_ + in_off + rb[i] + k0);
        const int kp = k0 >> 1;
        const ulonglong2 wA0 = *(const ulonglong2*)(Wp + kp * H_ + col);            // kpair kp, cols c,c+1
        const ulonglong2 wA1 = *(const ulonglong2*)(Wp + kp * H_ + col + 2);        // cols c+2,c+3
        const ulonglong2 wB0 = *(const ulonglong2*)(Wp + (kp + 1) * H_ + col);      // kpair kp+1
        const ulonglong2 wB1 = *(const ulonglong2*)(Wp + (kp + 1) * H_ + col + 2);
#pragma unroll
        for (int i = 0; i < 4; i++) {
            ffma2(acc[i * 4 + 0], wA0.x, a[i].x);
            ffma2(acc[i * 4 + 1], wA0.y, a[i].x);
            ffma2(acc[i * 4 + 2], wA1.x, a[i].x);
            ffma2(acc[i * 4 + 3], wA1.y, a[i].x);
            ffma2(acc[i * 4 + 0], wB0.x, a[i].y);
            ffma2(acc[i * 4 + 1], wB0.y, a[i].y);
            ffma2(acc[i * 4 + 2], wB1.x, a[i].y);
            ffma2(acc[i * 4 + 3], wB1.y, a[i].y);
        }
    }
}

// Stage one 64x64 weight matrix into pair-interleaved u64 form.
__device__ __forceinline__ void stage_pairs(const float* __restrict__ W,
                                            unsigned long long* __restrict__ Wp,
                                            int tid) {
    for (int idx = tid; idx < (H_ * H_) / 2; idx += 256) {
        const int kp = idx >> 6;   // / H_
        const int c = idx & 63;
        Wp[idx] = pack2(W[(2 * kp) * H_ + c], W[(2 * kp + 1) * H_ + c]);
    }
}

// =====================================================================
// Main decoder kernel: grid (P/TP, B), 256 threads
// Thread tile: 4 points x 4 columns (tj = tid&15 -> cols, tp = tid>>4 -> rows)
// =====================================================================
__global__ __launch_bounds__(256, 2)
void vson_decoder_kernel(const float* __restrict__ p,
                         const float* __restrict__ pos,
                         const float* __restrict__ W0,
                         const float* __restrict__ Wa,
                         const float* __restrict__ ba,
                         const float* __restrict__ Wb,
                         const float* __restrict__ bb,
                         const float* __restrict__ Wout,
                         const float* __restrict__ bout,
                         float* __restrict__ out) {
    extern __shared__ float sm[];
    const int tid = threadIdx.x;
    const int b = blockIdx.y;
    const int p0 = blockIdx.x * TP;

    // ---- stage block-0 weights (pair-interleaved) + misc into shared ----
    stage_pairs(Wa, (unsigned long long*)&sm[OFF_WPA], tid);
    stage_pairs(Wb, (unsigned long long*)&sm[OFF_WPB], tid);
    for (int i = tid; i < C_ * 3 * H_; i += 256) sm[OFF_M + i] = g_M[b * C_ * 3 * H_ + i];
    for (int i = tid; i < C_ * H_; i += 256)     sm[OFF_ZI + i] = g_zi[b * C_ * H_ + i];
    if (tid < H_) { sm[OFF_W0 + tid] = W0[tid]; sm[OFF_WOUT + tid] = Wout[tid]; }
    __syncthreads();

    // ---- per-point q (centered+clamped) and scalar s = |p_ext|^2 ----
    if (tid < TP) {
        const int pt = p0 + tid;
        const float* pp = p + ((size_t)b * P_ + pt) * 3;
        float q0 = pp[0] - pos[b * 3 + 0];
        float q1 = pp[1] - pos[b * 3 + 1];
        float q2 = pp[2] - pos[b * 3 + 2];
        float n = sqrtf(q0 * q0 + q1 * q1 + q2 * q2);
        if (n > 0.5f) { float sc = 0.5f / n; q0 *= sc; q1 *= sc; q2 *= sc; }
        float s = g_G[0] * q0 * q0 + g_G[4] * q1 * q1 + g_G[8] * q2 * q2
                + (g_G[1] + g_G[3]) * q0 * q1
                + (g_G[2] + g_G[6]) * q0 * q2
                + (g_G[5] + g_G[7]) * q1 * q2;
        ((float4*)&sm[OFF_QS])[tid] = make_float4(q0, q1, q2, s);
    }
    __syncthreads();

    const int tj = tid & 15;
    const int tp = tid >> 4;
    const int col = 4 * tj;
    int rb[4];
#pragma unroll
    for (int i = 0; i < 4; i++) rb[i] = (4 * tp + i) * XLD;

    float4 xres[4];   // raw x for this thread's (point,col) cells (residual path)
    float4 pool[4];
    unsigned long long acc[16];

    // =================== block 0 over C=8, with max-pool ===================
    for (int c = 0; c < C_; c++) {
        // X-stage: x = s*W0row0 + q.M[c] + zi_proj[c]; keep raw in regs, store relu
        {
            float4 w0 = *(const float4*)&sm[OFF_W0 + col];
            float4 m0 = *(const float4*)&sm[OFF_M + (c * 3 + 0) * H_ + col];
            float4 m1 = *(const float4*)&sm[OFF_M + (c * 3 + 1) * H_ + col];
            float4 m2 = *(const float4*)&sm[OFF_M + (c * 3 + 2) * H_ + col];
            float4 zz = *(const float4*)&sm[OFF_ZI + c * H_ + col];
#pragma unroll
            for (int i = 0; i < 4; i++) {
                float4 q = ((const float4*)&sm[OFF_QS])[4 * tp + i];
                float4 v;
                v.x = q.w * w0.x + q.x * m0.x + q.y * m1.x + q.z * m2.x + zz.x;
                v.y = q.w * w0.y + q.x * m0.y + q.y * m1.y + q.z * m2.y + zz.y;
                v.z = q.w * w0.z + q.x * m0.z + q.y * m1.z + q.z * m2.z + zz.z;
                v.w = q.w * w0.w + q.x * m0.w + q.y * m1.w + q.z * m2.w + zz.w;
                xres[i] = v;
                *(float4*)&sm[OFF_XS + rb[i] + col] =
                    make_float4(fmaxf(v.x, 0.f), fmaxf(v.y, 0.f),
                                fmaxf(v.z, 0.f), fmaxf(v.w, 0.f));
            }
        }
        __syncthreads();

        // H-stage: h = relu(x) @ Wa0 + ba0 ; store relu(h)
#pragma unroll
        for (int a = 0; a < 16; a++) acc[a] = 0ull;
        gemv64_pair(sm, OFF_XS, OFF_WPA, rb, col, acc);
        {
            const float4 bav = *(const float4*)(ba + col);
#pragma unroll
            for (int i = 0; i < 4; i++) {
                float4 h;
                h.x = fmaxf(red2(acc[i * 4 + 0]) + bav.x, 0.f);
                h.y = fmaxf(red2(acc[i * 4 + 1]) + bav.y, 0.f);
                h.z = fmaxf(red2(acc[i * 4 + 2]) + bav.z, 0.f);
                h.w = fmaxf(red2(acc[i * 4 + 3]) + bav.w, 0.f);
                *(float4*)&sm[OFF_HS + rb[i] + col] = h;
            }
        }
        __syncthreads();

        // Y-stage: y = relu(h) @ Wb0 + bb0 + x ; pool = max(pool, y)
#pragma unroll
        for (int a = 0; a < 16; a++) acc[a] = 0ull;
        gemv64_pair(sm, OFF_HS, OFF_WPB, rb, col, acc);
        {
            const float4 bbv = *(const float4*)(bb + col);
#pragma unroll
            for (int i = 0; i < 4; i++) {
                float4 y;
                y.x = red2(acc[i * 4 + 0]) + bbv.x + xres[i].x;
                y.y = red2(acc[i * 4 + 1]) + bbv.y + xres[i].y;
                y.z = red2(acc[i * 4 + 2]) + bbv.z + xres[i].z;
                y.w = red2(acc[i * 4 + 3]) + bbv.w + xres[i].w;
                if (c == 0) {
                    pool[i] = y;
                } else {
                    pool[i].x = fmaxf(pool[i].x, y.x);
                    pool[i].y = fmaxf(pool[i].y, y.y);
                    pool[i].z = fmaxf(pool[i].z, y.z);
                    pool[i].w = fmaxf(pool[i].w, y.w);
                }
            }
        }
        // no sync needed here: Y-stage reads only HS + registers; the next
        // X-stage writes only this thread's own XS cells, and the barrier
        // after X orders those writes (and everyone's Y completion) before
        // H-stage touches XS/HS again.
    }

    // pooled -> regs (residual) + relu(pool) -> XS
#pragma unroll
    for (int i = 0; i < 4; i++) {
        xres[i] = pool[i];
        *(float4*)&sm[OFF_XS + rb[i] + col] =
            make_float4(fmaxf(pool[i].x, 0.f), fmaxf(pool[i].y, 0.f),
                        fmaxf(pool[i].z, 0.f), fmaxf(pool[i].w, 0.f));
    }
    __syncthreads();

    // =================== residual blocks 1..4 ===================
    for (int l = 1; l < 5; l++) {
        __syncthreads();  // all GEMV reads of WPA/WPB done before restage
        stage_pairs(Wa + l * H_ * H_, (unsigned long long*)&sm[OFF_WPA], tid);
        stage_pairs(Wb + l * H_ * H_, (unsigned long long*)&sm[OFF_WPB], tid);
        __syncthreads();

        // H-stage
#pragma unroll
        for (int a = 0; a < 16; a++) acc[a] = 0ull;
        gemv64_pair(sm, OFF_XS, OFF_WPA, rb, col, acc);
        {
            const float4 bav = *(const float4*)(ba + l * H_ + col);
#pragma unroll
            for (int i = 0; i < 4; i++) {
                float4 h;
                h.x = fmaxf(red2(acc[i * 4 + 0]) + bav.x, 0.f);
                h.y = fmaxf(red2(acc[i * 4 + 1]) + bav.y, 0.f);
                h.z = fmaxf(red2(acc[i * 4 + 2]) + bav.z, 0.f);
                h.w = fmaxf(red2(acc[i * 4 + 3]) + bav.w, 0.f);
                *(float4*)&sm[OFF_HS + rb[i] + col] = h;
            }
        }
        __syncthreads();

        // Y-stage: x = relu(h) @ Wb + bb + x ; keep raw in regs, store relu
#pragma unroll
        for (int a = 0; a < 16; a++) acc[a] = 0ull;
        gemv64_pair(sm, OFF_HS, OFF_WPB, rb, col, acc);
        {
            const float4 bbv = *(const float4*)(bb + l * H_ + col);
#pragma unroll
            for (int i = 0; i < 4; i++) {
                float4 y;
                y.x = red2(acc[i * 4 + 0]) + bbv.x + xres[i].x;
                y.y = red2(acc[i * 4 + 1]) + bbv.y + xres[i].y;
                y.z = red2(acc[i * 4 + 2]) + bbv.z + xres[i].z;
                y.w = red2(acc[i * 4 + 3]) + bbv.w + xres[i].w;
                xres[i] = y;
                *(float4*)&sm[OFF_XS + rb[i] + col] =
                    make_float4(fmaxf(y.x, 0.f), fmaxf(y.y, 0.f),
                                fmaxf(y.z, 0.f), fmaxf(y.w, 0.f));
            }
        }
    }
    __syncthreads();

    // =================== output head (XS already relu'd) ===================
    if (tid < TP) {
        float acc0 = bout[0];
        const float4* xr = (const float4*)&sm[OFF_XS + tid * XLD];
        const float4* wv = (const float4*)&sm[OFF_WOUT];
#pragma unroll
        for (int j = 0; j < H_ / 4; j++) {
            float4 x4 = xr[j];
            float4 w4 = wv[j];
            acc0 += x4.x * w4.x + x4.y * w4.y + x4.z * w4.z + x4.w * w4.w;
        }
        out[(size_t)b * P_ + p0 + tid] = acc0;
    }
}

// =====================================================================
// Launch
// Inputs (metadata order): z, pos, p, W_feat, W_dir, W0, b0, Wa, ba, Wb, bb, Wout, bout
// =====================================================================
extern "C" void kernel_launch(void* const* d_in, const int* in_sizes, int n_in,
                              void* d_out, int out_size) {
    const float* z      = (const float*)d_in[0];
    const float* pos    = (const float*)d_in[1];
    const float* p      = (const float*)d_in[2];
    const float* W_feat = (const float*)d_in[3];
    const float* W_dir  = (const float*)d_in[4];
    const float* W0     = (const float*)d_in[5];
    const float* b0     = (const float*)d_in[6];
    const float* Wa     = (const float*)d_in[7];
    const float* ba     = (const float*)d_in[8];
    const float* Wb     = (const float*)d_in[9];
    const float* bb     = (const float*)d_in[10];
    const float* Wout   = (const float*)d_in[11];
    const float* bout   = (const float*)d_in[12];
    float* out = (float*)d_out;

    // Set the >48KB dynamic-smem opt-in only OUTSIDE graph capture. The
    // attribute is sticky per function+device, so setting it on the
    // (uncaptured) correctness call covers all later captured replays.
    cudaStreamCaptureStatus cap = cudaStreamCaptureStatusNone;
    cudaStreamIsCapturing((cudaStream_t)0, &cap);
    if (cap == cudaStreamCaptureStatusNone) {
        cudaFuncSetAttribute(vson_decoder_kernel,
                             cudaFuncAttributeMaxDynamicSharedMemorySize, SMEM_BYTES);
    }

    vson_precompute_kernel<<<B_ * C_, 64>>>(z, W_feat, W_dir, W0, b0);

    dim3 grid(P_ / TP, B_);
    vson_decoder_kernel<<<grid, 256, SMEM_BYTES>>>(p, pos, W0, Wa, ba, Wb, bb,
                                                   Wout, bout, out);
}